// round 15
// baseline (speedup 1.0000x reference)
#include <cuda_runtime.h>
#include <cstdint>

#define CN 50000
#define CE 600000
#define CEP (CE + CN)

// ---------------- device scratch (static: no allocations allowed) -----------
__device__ __align__(16) float g_h   [(size_t)CN * 128];
__device__ __align__(16) float g_xl  [(size_t)CN * 128];
__device__ __align__(16) float g_xr  [(size_t)CN * 128];
__device__ __align__(16) float g_loop[(size_t)CN * 16];
__device__ __align__(16) float g_csrea[(size_t)CEP * 16];   // edge_attr in CSR order
__device__ int g_is64;
__device__ __align__(16) int g_src[CE];
__device__ __align__(16) int g_dst[CE];
__device__ __align__(16) int g_cnt[CN];
__device__ __align__(16) int g_off[CN + 1];
__device__ __align__(16) int g_cur[CN];
__device__ __align__(16) int g_csr_eid[CEP];
__device__ __align__(16) int g_csr_src[CEP + 1];            // +1: prefetch pad
__device__ int g_bsum[64];
__device__ int g_bpre[64];
__device__ int g_total;

// ---------------- f32x2 packed helpers (sm_10x) ------------------------------
__device__ __forceinline__ unsigned long long pk2(float lo, float hi){
    unsigned long long r;
    asm("mov.b64 %0, {%1,%2};" : "=l"(r) : "f"(lo), "f"(hi));
    return r;
}
__device__ __forceinline__ void upk2(unsigned long long v, float& lo, float& hi){
    asm("mov.b64 {%0,%1}, %2;" : "=f"(lo), "=f"(hi) : "l"(v));
}
__device__ __forceinline__ unsigned long long fma2(unsigned long long a, unsigned long long b, unsigned long long c){
    unsigned long long d;
    asm("fma.rn.f32x2 %0, %1, %2, %3;" : "=l"(d) : "l"(a), "l"(b), "l"(c));
    return d;
}
__device__ __forceinline__ unsigned long long add2(unsigned long long a, unsigned long long b){
    unsigned long long d;
    asm("add.rn.f32x2 %0, %1, %2;" : "=l"(d) : "l"(a), "l"(b));
    return d;
}

// ---------------- index dtype detection + normalization ---------------------
__global__ void k_detect(const int* __restrict__ idx){
    __shared__ int s_or;
    if (threadIdx.x == 0) s_or = 0;
    __syncthreads();
    int v = 0;
    for (int i = threadIdx.x; i < 1024; i += blockDim.x) v |= idx[2 * i + 1];
    atomicOr(&s_or, v);
    __syncthreads();
    if (threadIdx.x == 0) g_is64 = (s_or == 0) ? 1 : 0;
}

__global__ void k_initcnt(int N){
    int i = blockIdx.x * blockDim.x + threadIdx.x;
    if (i < N) g_cnt[i] = 1;          // self loop pre-counted
}

// convert + histogram fused (initcnt must run before this)
__global__ void k_convert(const int* __restrict__ idx, int E){
    int e = blockIdx.x * blockDim.x + threadIdx.x;
    if (e >= E) return;
    int s, d;
    if (g_is64){
        s = idx[2 * e];
        d = idx[2 * (E + e)];
    } else {
        s = idx[e];
        d = idx[E + e];
    }
    g_src[e] = s;
    g_dst[e] = d;
    atomicAdd(&g_cnt[d], 1);
}

__global__ void k_scan1(int N){
    __shared__ int warpsum[32];
    int tid = threadIdx.x, lane = tid & 31, wid = tid >> 5;
    int i = blockIdx.x * 1024 + tid;
    int v = (i < N) ? g_cnt[i] : 0;
    int x = v;
    #pragma unroll
    for (int off = 1; off < 32; off <<= 1){
        int t = __shfl_up_sync(~0u, x, off);
        if (lane >= off) x += t;
    }
    if (lane == 31) warpsum[wid] = x;
    __syncthreads();
    if (wid == 0){
        int w = warpsum[lane];
        #pragma unroll
        for (int off = 1; off < 32; off <<= 1){
            int t = __shfl_up_sync(~0u, w, off);
            if (lane >= off) w += t;
        }
        warpsum[lane] = w;
    }
    __syncthreads();
    int wb = (wid > 0) ? warpsum[wid - 1] : 0;
    if (i < N) g_off[i] = wb + x - v;
    if (tid == 1023) g_bsum[blockIdx.x] = wb + x;
}

__global__ void k_scan2(int NB){
    int lane = threadIdx.x;
    int acc = 0;
    for (int base = 0; base < NB; base += 32){
        int idx = base + lane;
        int v = (idx < NB) ? g_bsum[idx] : 0;
        int x = v;
        #pragma unroll
        for (int off = 1; off < 32; off <<= 1){
            int t = __shfl_up_sync(~0u, x, off);
            if (lane >= off) x += t;
        }
        if (idx < NB) g_bpre[idx] = acc + x - v;
        acc += __shfl_sync(~0u, x, 31);
    }
    if (lane == 0) g_total = acc;
}

__global__ void k_scan3(int N){
    int i = blockIdx.x * blockDim.x + threadIdx.x;
    if (i < N){
        int v = g_off[i] + g_bpre[i >> 10];
        g_off[i] = v;
        g_cur[i] = v;
    }
    if (i == 0){
        g_off[N] = g_total;
        g_csr_src[g_total] = 0;       // prefetch pad (valid node index)
    }
}

__global__ void k_scatter(int E, int EP){
    int e = blockIdx.x * blockDim.x + threadIdx.x;
    if (e >= EP) return;
    int d, s;
    if (e < E){ d = g_dst[e]; s = g_src[e]; }
    else      { d = e - E;    s = d; }
    int pos = atomicAdd(&g_cur[d], 1);
    g_csr_eid[pos] = e;
    g_csr_src[pos] = s;
}

// ---------------- self-loop attr = mean of incoming edge_attr ----------------
__global__ void k_loopattr(const float* __restrict__ ea, int E, int N){
    int lane = threadIdx.x & 31;
    int node = (blockIdx.x * blockDim.x + threadIdx.x) >> 5;
    if (node >= N) return;
    int beg = g_off[node], end = g_off[node + 1];
    float sum = 0.f;
    for (int p = beg; p < end; p++){
        int eid = g_csr_eid[p];
        if (eid < E && lane < 16) sum += ea[(size_t)eid * 16 + lane];
    }
    float inv = 1.f / fmaxf((float)(end - beg - 1), 1.f);
    if (lane < 16) g_loop[node * 16 + lane] = sum * inv;
}

// ---------------- materialize edge_attr in CSR order -------------------------
__global__ void k_gatherea(const float* __restrict__ ea, int E, int EP){
    int idx = blockIdx.x * blockDim.x + threadIdx.x;
    if (idx >= EP * 4) return;
    int pos = idx >> 2, c = idx & 3;
    int eid = g_csr_eid[pos];
    const float4* sp = (eid < E) ? (const float4*)(ea + (size_t)eid * 16)
                                 : (const float4*)(g_loop + (size_t)(eid - E) * 16);
    ((float4*)g_csrea)[(size_t)pos * 4 + c] = sp[c];
}

// ---------------- GEMM (f32x2): g_h[M,128] = A[M,128] @ W[128,128] + b ------
__global__ void k_gemm128(const float* __restrict__ A, const float* __restrict__ W,
                          const float* __restrict__ b, int M){
    __shared__ ulonglong2 sA[512];
    int row0 = blockIdx.x * 16;
    int t = threadIdx.x;
    const ulonglong2* A4 = (const ulonglong2*)A;
    for (int i = t; i < 512; i += 128){
        int r = i >> 5, c = i & 31;
        ulonglong2 z; z.x = 0ULL; z.y = 0ULL;
        sA[i] = (row0 + r < M) ? A4[(size_t)(row0 + r) * 32 + c] : z;
    }
    __syncthreads();
    unsigned long long acc[16];
    #pragma unroll
    for (int r = 0; r < 16; r++) acc[r] = 0ULL;
    #pragma unroll 4
    for (int k4 = 0; k4 < 32; k4++){
        int kb = k4 * 512 + t;
        float w0 = W[kb], w1 = W[kb + 128], w2 = W[kb + 256], w3 = W[kb + 384];
        unsigned long long w01 = pk2(w0, w1), w23 = pk2(w2, w3);
        #pragma unroll
        for (int r = 0; r < 16; r++){
            ulonglong2 a = sA[r * 32 + k4];
            acc[r] = fma2(a.x, w01, acc[r]);
            acc[r] = fma2(a.y, w23, acc[r]);
        }
    }
    float bv = b[t];
    #pragma unroll
    for (int r = 0; r < 16; r++){
        if (row0 + r < M){
            float lo, hi; upk2(acc[r], lo, hi);
            g_h[(size_t)(row0 + r) * 128 + t] = lo + hi + bv;
        }
    }
}

__global__ void k_dualgemm(const float* __restrict__ Wl, const float* __restrict__ bl,
                           const float* __restrict__ Wr, const float* __restrict__ br, int M){
    __shared__ ulonglong2 sA[512];
    int row0 = blockIdx.x * 16;
    int t = threadIdx.x;
    const ulonglong2* A4 = (const ulonglong2*)g_h;
    for (int i = t; i < 512; i += 128){
        int r = i >> 5, c = i & 31;
        ulonglong2 z; z.x = 0ULL; z.y = 0ULL;
        sA[i] = (row0 + r < M) ? A4[(size_t)(row0 + r) * 32 + c] : z;
    }
    __syncthreads();
    unsigned long long accL[16], accR[16];
    #pragma unroll
    for (int r = 0; r < 16; r++){ accL[r] = 0ULL; accR[r] = 0ULL; }
    #pragma unroll 4
    for (int k4 = 0; k4 < 32; k4++){
        int kb = k4 * 512 + t;
        float l0 = Wl[kb], l1 = Wl[kb + 128], l2 = Wl[kb + 256], l3 = Wl[kb + 384];
        float r0 = Wr[kb], r1 = Wr[kb + 128], r2 = Wr[kb + 256], r3 = Wr[kb + 384];
        unsigned long long l01 = pk2(l0, l1), l23 = pk2(l2, l3);
        unsigned long long r01 = pk2(r0, r1), r23 = pk2(r2, r3);
        #pragma unroll
        for (int r = 0; r < 16; r++){
            ulonglong2 a = sA[r * 32 + k4];
            accL[r] = fma2(a.x, l01, accL[r]);
            accL[r] = fma2(a.y, l23, accL[r]);
            accR[r] = fma2(a.x, r01, accR[r]);
            accR[r] = fma2(a.y, r23, accR[r]);
        }
    }
    float bL = bl[t], bR = br[t];
    #pragma unroll
    for (int r = 0; r < 16; r++){
        if (row0 + r < M){
            float lo, hi;
            upk2(accL[r], lo, hi);
            g_xl[(size_t)(row0 + r) * 128 + t] = lo + hi + bL;
            upk2(accR[r], lo, hi);
            g_xr[(size_t)(row0 + r) * 128 + t] = lo + hi + bR;
        }
    }
}

// ---------------- fused edge phase: persistent warps, warp per node ----------
// Lane owns 4 channels (col = 4*lane). ee-dot packed over j pairs.
__global__ void __launch_bounds__(256, 2)
k_edge_fused(const float* __restrict__ We_l, const float* __restrict__ att_l,
             const float* __restrict__ cb_l, int N){
    int lane = threadIdx.x & 31;
    int wg   = (blockIdx.x * blockDim.x + threadIdx.x) >> 5;
    int nw   = (gridDim.x * blockDim.x) >> 5;
    int col  = lane << 2;

    float4 attv = ((const float4*)att_l)[lane];
    float4 cbv  = ((const float4*)cb_l)[lane];
    unsigned long long we0[8], we1[8], we2[8], we3[8];
    #pragma unroll
    for (int j = 0; j < 8; j++){
        const float* r0 = We_l + (2 * j) * 128 + col;
        const float* r1 = We_l + (2 * j + 1) * 128 + col;
        we0[j] = pk2(r0[0], r1[0]);
        we1[j] = pk2(r0[1], r1[1]);
        we2[j] = pk2(r0[2], r1[2]);
        we3[j] = pk2(r0[3], r1[3]);
    }

    for (int node = wg; node < N; node += nw){
        ulonglong2 xr2 = ((const ulonglong2*)(g_xr + (size_t)node * 128))[lane];
        int beg = g_off[node], end = g_off[node + 1];   // end > beg (self loop)

        float den = 0.f;
        unsigned long long acc01 = 0ULL, acc23 = 0ULL;

        int sfirst = g_csr_src[beg];
        ulonglong2 xln = ((const ulonglong2*)(g_xl + (size_t)sfirst * 128))[lane];

        #pragma unroll 2
        for (int p = beg; p < end; p++){
            ulonglong2 xlc = xln;
            int sn = g_csr_src[p + 1];                // padded: always valid
            xln = ((const ulonglong2*)(g_xl + (size_t)sn * 128))[lane];

            const ulonglong2* ap = (const ulonglong2*)(g_csrea + (size_t)p * 16);
            ulonglong2 pa = ap[0], pb = ap[1];
            unsigned long long pr[8] = {pa.x, pa.y, pb.x, pb.y, 0ULL, 0ULL, 0ULL, 0ULL};
            ulonglong2 pc2 = ap[2], pd = ap[3];
            pr[4] = pc2.x; pr[5] = pc2.y; pr[6] = pd.x; pr[7] = pd.y;

            // 4 independent packed chains, one per channel
            unsigned long long s0 = 0ULL, s1 = 0ULL, s2 = 0ULL, s3 = 0ULL;
            #pragma unroll
            for (int j = 0; j < 8; j++){
                s0 = fma2(pr[j], we0[j], s0);
                s1 = fma2(pr[j], we1[j], s1);
                s2 = fma2(pr[j], we2[j], s2);
                s3 = fma2(pr[j], we3[j], s3);
            }
            float e0l, e0h, e1l, e1h, e2l, e2h, e3l, e3h;
            upk2(s0, e0l, e0h); upk2(s1, e1l, e1h);
            upk2(s2, e2l, e2h); upk2(s3, e3l, e3h);

            unsigned long long x01 = add2(xlc.x, xr2.x);
            unsigned long long x23 = add2(xlc.y, xr2.y);
            float m0, m1, m2, m3;
            upk2(x01, m0, m1); upk2(x23, m2, m3);
            m0 += e0l + e0h;
            m1 += e1l + e1h;
            m2 += e2l + e2h;
            m3 += e3l + e3h;
            m0 = fmaxf(m0, 0.2f * m0);      // LeakyReLU(0.2)
            m1 = fmaxf(m1, 0.2f * m1);
            m2 = fmaxf(m2, 0.2f * m2);
            m3 = fmaxf(m3, 0.2f * m3);
            float lg = fmaf(m0, attv.x, fmaf(m1, attv.y, fmaf(m2, attv.z, m3 * attv.w)));
            lg += __shfl_xor_sync(~0u, lg, 1);
            lg += __shfl_xor_sync(~0u, lg, 2);
            lg += __shfl_xor_sync(~0u, lg, 4);

            float w = __expf(lg);           // logits tiny: no max subtraction
            den += w;
            unsigned long long w2 = pk2(w, w);
            acc01 = fma2(xlc.x, w2, acc01);
            acc23 = fma2(xlc.y, w2, acc23);
        }

        float a0, a1, a2, a3;
        upk2(acc01, a0, a1); upk2(acc23, a2, a3);
        float inv = 1.f / den;
        float v0 = fmaf(a0, inv, cbv.x);
        float v1 = fmaf(a1, inv, cbv.y);
        float v2 = fmaf(a2, inv, cbv.z);
        float v3 = fmaf(a3, inv, cbv.w);
        float4 o;
        o.x = v0 > 0.f ? v0 : expm1f(v0);
        o.y = v1 > 0.f ? v1 : expm1f(v1);
        o.z = v2 > 0.f ? v2 : expm1f(v2);
        o.w = v3 > 0.f ? v3 : expm1f(v3);
        ((float4*)(g_h + (size_t)node * 128))[lane] = o;
    }
}

// ---------------- LayerNorm + MLP head (warp per node) ----------------------
__global__ void k_final(const float* __restrict__ lng, const float* __restrict__ lnb,
                        const float* __restrict__ h1w, const float* __restrict__ h1b,
                        const float* __restrict__ h2w, const float* __restrict__ h2b,
                        float* __restrict__ out, int N){
    __shared__ float s_w1[128 * 64];
    __shared__ float s_w2[64 * 3];
    int t = threadIdx.x;
    for (int i = t; i < 8192; i += 256) s_w1[i] = h1w[i];
    if (t < 192) s_w2[t] = h2w[t];
    __syncthreads();
    int warp = t >> 5, lane = t & 31;
    int node = blockIdx.x * 8 + warp;
    if (node >= N) return;
    const float* hrow = g_h + (size_t)node * 128;
    float hv[4];
    #pragma unroll
    for (int i = 0; i < 4; i++) hv[i] = hrow[lane + 32 * i];
    float s = hv[0] + hv[1] + hv[2] + hv[3];
    #pragma unroll
    for (int off = 16; off; off >>= 1) s += __shfl_xor_sync(~0u, s, off);
    float mu = s * (1.f / 128.f);
    float sq = 0.f;
    #pragma unroll
    for (int i = 0; i < 4; i++){ float dd = hv[i] - mu; sq += dd * dd; }
    #pragma unroll
    for (int off = 16; off; off >>= 1) sq += __shfl_xor_sync(~0u, sq, off);
    float rs = rsqrtf(sq * (1.f / 128.f) + 1e-5f);
    float y[4];
    #pragma unroll
    for (int i = 0; i < 4; i++){
        int c = lane + 32 * i;
        y[i] = (hv[i] - mu) * rs * lng[c] + lnb[c];
    }
    float a0 = h1b[lane], a1 = h1b[lane + 32];
    #pragma unroll
    for (int k = 0; k < 128; k++){
        float yv = __shfl_sync(~0u, y[k >> 5], k & 31);
        a0 = fmaf(yv, s_w1[k * 64 + lane     ], a0);
        a1 = fmaf(yv, s_w1[k * 64 + lane + 32], a1);
    }
    a0 = fmaxf(a0, 0.f); a1 = fmaxf(a1, 0.f);
    float p0 = a0 * s_w2[lane * 3 + 0] + a1 * s_w2[(lane + 32) * 3 + 0];
    float p1 = a0 * s_w2[lane * 3 + 1] + a1 * s_w2[(lane + 32) * 3 + 1];
    float p2 = a0 * s_w2[lane * 3 + 2] + a1 * s_w2[(lane + 32) * 3 + 2];
    #pragma unroll
    for (int off = 16; off; off >>= 1){
        p0 += __shfl_xor_sync(~0u, p0, off);
        p1 += __shfl_xor_sync(~0u, p1, off);
        p2 += __shfl_xor_sync(~0u, p2, off);
    }
    if (lane == 0){
        out[node * 3 + 0] = p0 + h2b[0];
        out[node * 3 + 1] = p1 + h2b[1];
        out[node * 3 + 2] = p2 + h2b[2];
    }
}

// ---------------- host orchestration ----------------------------------------
extern "C" void kernel_launch(void* const* d_in, const int* in_sizes, int n_in,
                              void* d_out, int out_size){
    const float* x     = (const float*)d_in[0];
    const int*   eidx  = (const int*)d_in[1];
    const float* eattr = (const float*)d_in[2];
    const float* in_w  = (const float*)d_in[3];
    const float* in_b  = (const float*)d_in[4];
    const float* Wl    = (const float*)d_in[5];
    const float* bl    = (const float*)d_in[6];
    const float* Wr    = (const float*)d_in[7];
    const float* br    = (const float*)d_in[8];
    const float* We    = (const float*)d_in[9];
    const float* att   = (const float*)d_in[10];
    const float* cb    = (const float*)d_in[11];
    const float* lng   = (const float*)d_in[12];
    const float* lnb   = (const float*)d_in[13];
    const float* h1w   = (const float*)d_in[14];
    const float* h1b   = (const float*)d_in[15];
    const float* h2w   = (const float*)d_in[16];
    const float* h2b   = (const float*)d_in[17];
    float* out = (float*)d_out;

    int N  = in_sizes[0] / 128;
    int E  = in_sizes[1] / 2;
    int EP = E + N;
    int NB = (N + 1023) / 1024;

    // edge index normalization + histogram (initcnt first)
    k_detect<<<1, 256>>>(eidx);
    k_initcnt<<<(N + 255) / 256, 256>>>(N);
    k_convert<<<(E + 255) / 256, 256>>>(eidx, E);

    // CSR build (by destination)
    k_scan1<<<NB, 1024>>>(N);
    k_scan2<<<1, 32>>>(NB);
    k_scan3<<<(N + 255) / 256, 256>>>(N);
    k_scatter<<<(EP + 255) / 256, 256>>>(E, EP);

    // self-loop attrs, CSR-ordered edge_attr
    k_loopattr<<<(N * 32 + 255) / 256, 256>>>(eattr, E, N);
    k_gatherea<<<(EP * 4 + 255) / 256, 256>>>(eattr, E, EP);

    // input projection -> g_h
    k_gemm128<<<(N + 15) / 16, 128>>>(x, in_w, in_b, N);

    for (int l = 0; l < 2; l++){
        const float* Wl_l  = Wl  + (size_t)l * 128 * 128;
        const float* bl_l  = bl  + (size_t)l * 128;
        const float* Wr_l  = Wr  + (size_t)l * 128 * 128;
        const float* br_l  = br  + (size_t)l * 128;
        const float* We_l  = We  + (size_t)l * 16 * 128;
        const float* att_l = att + (size_t)l * 128;
        const float* cb_l  = cb  + (size_t)l * 128;

        k_dualgemm<<<(N + 15) / 16, 128>>>(Wl_l, bl_l, Wr_l, br_l, N);
        k_edge_fused<<<296, 256>>>(We_l, att_l, cb_l, N);
    }

    k_final<<<(N + 7) / 8, 256>>>(lng, lnb, h1w, h1b, h2w, h2b, out, N);
}

// round 16
// speedup vs baseline: 1.5133x; 1.5133x over previous
#include <cuda_runtime.h>
#include <cstdint>

#define CN 50000
#define CE 600000
#define CEP (CE + CN)

// ---------------- device scratch (static: no allocations allowed) -----------
__device__ __align__(16) float g_h   [(size_t)CN * 128];
__device__ __align__(16) float g_xl  [(size_t)CN * 128];
__device__ __align__(16) float g_xr  [(size_t)CN * 128];
__device__ __align__(16) float g_loop[(size_t)CN * 16];
__device__ __align__(16) float g_csrea[(size_t)CEP * 16];   // edge_attr in CSR order
__device__ int g_is64;
__device__ __align__(16) int g_src[CE];
__device__ __align__(16) int g_dst[CE];
__device__ __align__(16) int g_cnt[CN];
__device__ __align__(16) int g_off[CN + 1];
__device__ __align__(16) int g_cur[CN];
__device__ __align__(16) int g_csr_eid[CEP];
__device__ __align__(16) int g_csr_src[CEP];
__device__ int g_bsum[64];
__device__ int g_bpre[64];
__device__ int g_total;

// ---------------- f32x2 packed helpers (sm_10x) ------------------------------
__device__ __forceinline__ unsigned long long pk2(float lo, float hi){
    unsigned long long r;
    asm("mov.b64 %0, {%1,%2};" : "=l"(r) : "f"(lo), "f"(hi));
    return r;
}
__device__ __forceinline__ void upk2(unsigned long long v, float& lo, float& hi){
    asm("mov.b64 {%0,%1}, %2;" : "=f"(lo), "=f"(hi) : "l"(v));
}
__device__ __forceinline__ unsigned long long fma2(unsigned long long a, unsigned long long b, unsigned long long c){
    unsigned long long d;
    asm("fma.rn.f32x2 %0, %1, %2, %3;" : "=l"(d) : "l"(a), "l"(b), "l"(c));
    return d;
}
__device__ __forceinline__ unsigned long long add2(unsigned long long a, unsigned long long b){
    unsigned long long d;
    asm("add.rn.f32x2 %0, %1, %2;" : "=l"(d) : "l"(a), "l"(b));
    return d;
}

// ---------------- index dtype detection + normalization ---------------------
__global__ void k_detect(const int* __restrict__ idx){
    __shared__ int s_or;
    if (threadIdx.x == 0) s_or = 0;
    __syncthreads();
    int v = 0;
    for (int i = threadIdx.x; i < 1024; i += blockDim.x) v |= idx[2 * i + 1];
    atomicOr(&s_or, v);
    __syncthreads();
    if (threadIdx.x == 0) g_is64 = (s_or == 0) ? 1 : 0;
}

__global__ void k_initcnt(int N){
    int i = blockIdx.x * blockDim.x + threadIdx.x;
    if (i < N) g_cnt[i] = 1;          // self loop pre-counted
}

// convert + histogram fused (initcnt must run before this)
__global__ void k_convert(const int* __restrict__ idx, int E){
    int e = blockIdx.x * blockDim.x + threadIdx.x;
    if (e >= E) return;
    int s, d;
    if (g_is64){
        s = idx[2 * e];
        d = idx[2 * (E + e)];
    } else {
        s = idx[e];
        d = idx[E + e];
    }
    g_src[e] = s;
    g_dst[e] = d;
    atomicAdd(&g_cnt[d], 1);
}

__global__ void k_scan1(int N){
    __shared__ int warpsum[32];
    int tid = threadIdx.x, lane = tid & 31, wid = tid >> 5;
    int i = blockIdx.x * 1024 + tid;
    int v = (i < N) ? g_cnt[i] : 0;
    int x = v;
    #pragma unroll
    for (int off = 1; off < 32; off <<= 1){
        int t = __shfl_up_sync(~0u, x, off);
        if (lane >= off) x += t;
    }
    if (lane == 31) warpsum[wid] = x;
    __syncthreads();
    if (wid == 0){
        int w = warpsum[lane];
        #pragma unroll
        for (int off = 1; off < 32; off <<= 1){
            int t = __shfl_up_sync(~0u, w, off);
            if (lane >= off) w += t;
        }
        warpsum[lane] = w;
    }
    __syncthreads();
    int wb = (wid > 0) ? warpsum[wid - 1] : 0;
    if (i < N) g_off[i] = wb + x - v;
    if (tid == 1023) g_bsum[blockIdx.x] = wb + x;
}

__global__ void k_scan2(int NB){
    int lane = threadIdx.x;
    int acc = 0;
    for (int base = 0; base < NB; base += 32){
        int idx = base + lane;
        int v = (idx < NB) ? g_bsum[idx] : 0;
        int x = v;
        #pragma unroll
        for (int off = 1; off < 32; off <<= 1){
            int t = __shfl_up_sync(~0u, x, off);
            if (lane >= off) x += t;
        }
        if (idx < NB) g_bpre[idx] = acc + x - v;
        acc += __shfl_sync(~0u, x, 31);
    }
    if (lane == 0) g_total = acc;
}

__global__ void k_scan3(int N){
    int i = blockIdx.x * blockDim.x + threadIdx.x;
    if (i < N){
        int v = g_off[i] + g_bpre[i >> 10];
        g_off[i] = v;
        g_cur[i] = v;
    }
    if (i == 0) g_off[N] = g_total;
}

__global__ void k_scatter(int E, int EP){
    int e = blockIdx.x * blockDim.x + threadIdx.x;
    if (e >= EP) return;
    int d, s;
    if (e < E){ d = g_dst[e]; s = g_src[e]; }
    else      { d = e - E;    s = d; }
    int pos = atomicAdd(&g_cur[d], 1);
    g_csr_eid[pos] = e;
    g_csr_src[pos] = s;
}

// ---------------- self-loop attr = mean of incoming edge_attr ----------------
__global__ void k_loopattr(const float* __restrict__ ea, int E, int N){
    int lane = threadIdx.x & 31;
    int node = (blockIdx.x * blockDim.x + threadIdx.x) >> 5;
    if (node >= N) return;
    int beg = g_off[node], end = g_off[node + 1];
    float sum = 0.f;
    for (int p = beg; p < end; p++){
        int eid = g_csr_eid[p];
        if (eid < E && lane < 16) sum += ea[(size_t)eid * 16 + lane];
    }
    float inv = 1.f / fmaxf((float)(end - beg - 1), 1.f);
    if (lane < 16) g_loop[node * 16 + lane] = sum * inv;
}

// ---------------- materialize edge_attr in CSR order -------------------------
__global__ void k_gatherea(const float* __restrict__ ea, int E, int EP){
    int idx = blockIdx.x * blockDim.x + threadIdx.x;
    if (idx >= EP * 4) return;
    int pos = idx >> 2, c = idx & 3;
    int eid = g_csr_eid[pos];
    const float4* sp = (eid < E) ? (const float4*)(ea + (size_t)eid * 16)
                                 : (const float4*)(g_loop + (size_t)(eid - E) * 16);
    ((float4*)g_csrea)[(size_t)pos * 4 + c] = sp[c];
}

// ---------------- GEMM (f32x2): g_h[M,128] = A[M,128] @ W[128,128] + b ------
__global__ void k_gemm128(const float* __restrict__ A, const float* __restrict__ W,
                          const float* __restrict__ b, int M){
    __shared__ ulonglong2 sA[512];
    int row0 = blockIdx.x * 16;
    int t = threadIdx.x;
    const ulonglong2* A4 = (const ulonglong2*)A;
    for (int i = t; i < 512; i += 128){
        int r = i >> 5, c = i & 31;
        ulonglong2 z; z.x = 0ULL; z.y = 0ULL;
        sA[i] = (row0 + r < M) ? A4[(size_t)(row0 + r) * 32 + c] : z;
    }
    __syncthreads();
    unsigned long long acc[16];
    #pragma unroll
    for (int r = 0; r < 16; r++) acc[r] = 0ULL;
    #pragma unroll 4
    for (int k4 = 0; k4 < 32; k4++){
        int kb = k4 * 512 + t;
        float w0 = W[kb], w1 = W[kb + 128], w2 = W[kb + 256], w3 = W[kb + 384];
        unsigned long long w01 = pk2(w0, w1), w23 = pk2(w2, w3);
        #pragma unroll
        for (int r = 0; r < 16; r++){
            ulonglong2 a = sA[r * 32 + k4];
            acc[r] = fma2(a.x, w01, acc[r]);
            acc[r] = fma2(a.y, w23, acc[r]);
        }
    }
    float bv = b[t];
    #pragma unroll
    for (int r = 0; r < 16; r++){
        if (row0 + r < M){
            float lo, hi; upk2(acc[r], lo, hi);
            g_h[(size_t)(row0 + r) * 128 + t] = lo + hi + bv;
        }
    }
}

__global__ void k_dualgemm(const float* __restrict__ Wl, const float* __restrict__ bl,
                           const float* __restrict__ Wr, const float* __restrict__ br, int M){
    __shared__ ulonglong2 sA[512];
    int row0 = blockIdx.x * 16;
    int t = threadIdx.x;
    const ulonglong2* A4 = (const ulonglong2*)g_h;
    for (int i = t; i < 512; i += 128){
        int r = i >> 5, c = i & 31;
        ulonglong2 z; z.x = 0ULL; z.y = 0ULL;
        sA[i] = (row0 + r < M) ? A4[(size_t)(row0 + r) * 32 + c] : z;
    }
    __syncthreads();
    unsigned long long accL[16], accR[16];
    #pragma unroll
    for (int r = 0; r < 16; r++){ accL[r] = 0ULL; accR[r] = 0ULL; }
    #pragma unroll 4
    for (int k4 = 0; k4 < 32; k4++){
        int kb = k4 * 512 + t;
        float l0 = Wl[kb], l1 = Wl[kb + 128], l2 = Wl[kb + 256], l3 = Wl[kb + 384];
        float r0 = Wr[kb], r1 = Wr[kb + 128], r2 = Wr[kb + 256], r3 = Wr[kb + 384];
        unsigned long long l01 = pk2(l0, l1), l23 = pk2(l2, l3);
        unsigned long long r01 = pk2(r0, r1), r23 = pk2(r2, r3);
        #pragma unroll
        for (int r = 0; r < 16; r++){
            ulonglong2 a = sA[r * 32 + k4];
            accL[r] = fma2(a.x, l01, accL[r]);
            accL[r] = fma2(a.y, l23, accL[r]);
            accR[r] = fma2(a.x, r01, accR[r]);
            accR[r] = fma2(a.y, r23, accR[r]);
        }
    }
    float bL = bl[t], bR = br[t];
    #pragma unroll
    for (int r = 0; r < 16; r++){
        if (row0 + r < M){
            float lo, hi;
            upk2(accL[r], lo, hi);
            g_xl[(size_t)(row0 + r) * 128 + t] = lo + hi + bL;
            upk2(accR[r], lo, hi);
            g_xr[(size_t)(row0 + r) * 128 + t] = lo + hi + bR;
        }
    }
}

// ---------------- fused edge phase: persistent warps, warp per node ----------
// Lane owns 4 channels (col = 4*lane). ee-dot packed over j pairs.
__global__ void __launch_bounds__(256, 2)
k_edge_fused(const float* __restrict__ We_l, const float* __restrict__ att_l,
             const float* __restrict__ cb_l, int N){
    int lane = threadIdx.x & 31;
    int wg   = (blockIdx.x * blockDim.x + threadIdx.x) >> 5;
    int nw   = (gridDim.x * blockDim.x) >> 5;
    int col  = lane << 2;

    float4 attv = ((const float4*)att_l)[lane];
    float4 cbv  = ((const float4*)cb_l)[lane];
    unsigned long long we0[8], we1[8], we2[8], we3[8];
    #pragma unroll
    for (int j = 0; j < 8; j++){
        const float* r0 = We_l + (2 * j) * 128 + col;
        const float* r1 = We_l + (2 * j + 1) * 128 + col;
        we0[j] = pk2(r0[0], r1[0]);
        we1[j] = pk2(r0[1], r1[1]);
        we2[j] = pk2(r0[2], r1[2]);
        we3[j] = pk2(r0[3], r1[3]);
    }

    for (int node = wg; node < N; node += nw){
        ulonglong2 xr2 = ((const ulonglong2*)(g_xr + (size_t)node * 128))[lane];
        int beg = g_off[node], end = g_off[node + 1];   // end > beg (self loop)

        float den = 0.f;
        unsigned long long acc01 = 0ULL, acc23 = 0ULL;

        int sfirst = g_csr_src[beg];
        ulonglong2 xln = ((const ulonglong2*)(g_xl + (size_t)sfirst * 128))[lane];

        #pragma unroll 2
        for (int p = beg; p < end; p++){
            ulonglong2 xlc = xln;
            int pn = (p + 1 < end) ? p + 1 : p;
            int sn = g_csr_src[pn];
            xln = ((const ulonglong2*)(g_xl + (size_t)sn * 128))[lane];

            const ulonglong2* ap = (const ulonglong2*)(g_csrea + (size_t)p * 16);
            ulonglong2 pa = ap[0], pb = ap[1];
            unsigned long long pr[8] = {pa.x, pa.y, pb.x, pb.y, 0ULL, 0ULL, 0ULL, 0ULL};
            ulonglong2 pc2 = ap[2], pd = ap[3];
            pr[4] = pc2.x; pr[5] = pc2.y; pr[6] = pd.x; pr[7] = pd.y;

            // 4 independent packed chains, one per channel
            unsigned long long s0 = 0ULL, s1 = 0ULL, s2 = 0ULL, s3 = 0ULL;
            #pragma unroll
            for (int j = 0; j < 8; j++){
                s0 = fma2(pr[j], we0[j], s0);
                s1 = fma2(pr[j], we1[j], s1);
                s2 = fma2(pr[j], we2[j], s2);
                s3 = fma2(pr[j], we3[j], s3);
            }
            float e0l, e0h, e1l, e1h, e2l, e2h, e3l, e3h;
            upk2(s0, e0l, e0h); upk2(s1, e1l, e1h);
            upk2(s2, e2l, e2h); upk2(s3, e3l, e3h);

            unsigned long long x01 = add2(xlc.x, xr2.x);
            unsigned long long x23 = add2(xlc.y, xr2.y);
            float m0, m1, m2, m3;
            upk2(x01, m0, m1); upk2(x23, m2, m3);
            m0 += e0l + e0h;
            m1 += e1l + e1h;
            m2 += e2l + e2h;
            m3 += e3l + e3h;
            m0 = fmaxf(m0, 0.2f * m0);      // LeakyReLU(0.2)
            m1 = fmaxf(m1, 0.2f * m1);
            m2 = fmaxf(m2, 0.2f * m2);
            m3 = fmaxf(m3, 0.2f * m3);
            float lg = fmaf(m0, attv.x, fmaf(m1, attv.y, fmaf(m2, attv.z, m3 * attv.w)));
            lg += __shfl_xor_sync(~0u, lg, 1);
            lg += __shfl_xor_sync(~0u, lg, 2);
            lg += __shfl_xor_sync(~0u, lg, 4);

            float w = __expf(lg);           // logits tiny: no max subtraction
            den += w;
            unsigned long long w2 = pk2(w, w);
            acc01 = fma2(xlc.x, w2, acc01);
            acc23 = fma2(xlc.y, w2, acc23);
        }

        float a0, a1, a2, a3;
        upk2(acc01, a0, a1); upk2(acc23, a2, a3);
        float inv = 1.f / den;
        float v0 = fmaf(a0, inv, cbv.x);
        float v1 = fmaf(a1, inv, cbv.y);
        float v2 = fmaf(a2, inv, cbv.z);
        float v3 = fmaf(a3, inv, cbv.w);
        float4 o;
        o.x = v0 > 0.f ? v0 : expm1f(v0);
        o.y = v1 > 0.f ? v1 : expm1f(v1);
        o.z = v2 > 0.f ? v2 : expm1f(v2);
        o.w = v3 > 0.f ? v3 : expm1f(v3);
        ((float4*)(g_h + (size_t)node * 128))[lane] = o;
    }
}

// ---------------- LayerNorm + MLP head (warp per node) ----------------------
__global__ void k_final(const float* __restrict__ lng, const float* __restrict__ lnb,
                        const float* __restrict__ h1w, const float* __restrict__ h1b,
                        const float* __restrict__ h2w, const float* __restrict__ h2b,
                        float* __restrict__ out, int N){
    __shared__ float s_w1[128 * 64];
    __shared__ float s_w2[64 * 3];
    int t = threadIdx.x;
    for (int i = t; i < 8192; i += 256) s_w1[i] = h1w[i];
    if (t < 192) s_w2[t] = h2w[t];
    __syncthreads();
    int warp = t >> 5, lane = t & 31;
    int node = blockIdx.x * 8 + warp;
    if (node >= N) return;
    const float* hrow = g_h + (size_t)node * 128;
    float hv[4];
    #pragma unroll
    for (int i = 0; i < 4; i++) hv[i] = hrow[lane + 32 * i];
    float s = hv[0] + hv[1] + hv[2] + hv[3];
    #pragma unroll
    for (int off = 16; off; off >>= 1) s += __shfl_xor_sync(~0u, s, off);
    float mu = s * (1.f / 128.f);
    float sq = 0.f;
    #pragma unroll
    for (int i = 0; i < 4; i++){ float dd = hv[i] - mu; sq += dd * dd; }
    #pragma unroll
    for (int off = 16; off; off >>= 1) sq += __shfl_xor_sync(~0u, sq, off);
    float rs = rsqrtf(sq * (1.f / 128.f) + 1e-5f);
    float y[4];
    #pragma unroll
    for (int i = 0; i < 4; i++){
        int c = lane + 32 * i;
        y[i] = (hv[i] - mu) * rs * lng[c] + lnb[c];
    }
    float a0 = h1b[lane], a1 = h1b[lane + 32];
    #pragma unroll
    for (int k = 0; k < 128; k++){
        float yv = __shfl_sync(~0u, y[k >> 5], k & 31);
        a0 = fmaf(yv, s_w1[k * 64 + lane     ], a0);
        a1 = fmaf(yv, s_w1[k * 64 + lane + 32], a1);
    }
    a0 = fmaxf(a0, 0.f); a1 = fmaxf(a1, 0.f);
    float p0 = a0 * s_w2[lane * 3 + 0] + a1 * s_w2[(lane + 32) * 3 + 0];
    float p1 = a0 * s_w2[lane * 3 + 1] + a1 * s_w2[(lane + 32) * 3 + 1];
    float p2 = a0 * s_w2[lane * 3 + 2] + a1 * s_w2[(lane + 32) * 3 + 2];
    #pragma unroll
    for (int off = 16; off; off >>= 1){
        p0 += __shfl_xor_sync(~0u, p0, off);
        p1 += __shfl_xor_sync(~0u, p1, off);
        p2 += __shfl_xor_sync(~0u, p2, off);
    }
    if (lane == 0){
        out[node * 3 + 0] = p0 + h2b[0];
        out[node * 3 + 1] = p1 + h2b[1];
        out[node * 3 + 2] = p2 + h2b[2];
    }
}

// ---------------- host orchestration ----------------------------------------
extern "C" void kernel_launch(void* const* d_in, const int* in_sizes, int n_in,
                              void* d_out, int out_size){
    const float* x     = (const float*)d_in[0];
    const int*   eidx  = (const int*)d_in[1];
    const float* eattr = (const float*)d_in[2];
    const float* in_w  = (const float*)d_in[3];
    const float* in_b  = (const float*)d_in[4];
    const float* Wl    = (const float*)d_in[5];
    const float* bl    = (const float*)d_in[6];
    const float* Wr    = (const float*)d_in[7];
    const float* br    = (const float*)d_in[8];
    const float* We    = (const float*)d_in[9];
    const float* att   = (const float*)d_in[10];
    const float* cb    = (const float*)d_in[11];
    const float* lng   = (const float*)d_in[12];
    const float* lnb   = (const float*)d_in[13];
    const float* h1w   = (const float*)d_in[14];
    const float* h1b   = (const float*)d_in[15];
    const float* h2w   = (const float*)d_in[16];
    const float* h2b   = (const float*)d_in[17];
    float* out = (float*)d_out;

    int N  = in_sizes[0] / 128;
    int E  = in_sizes[1] / 2;
    int EP = E + N;
    int NB = (N + 1023) / 1024;

    // edge index normalization + histogram (initcnt first)
    k_detect<<<1, 256>>>(eidx);
    k_initcnt<<<(N + 255) / 256, 256>>>(N);
    k_convert<<<(E + 255) / 256, 256>>>(eidx, E);

    // CSR build (by destination)
    k_scan1<<<NB, 1024>>>(N);
    k_scan2<<<1, 32>>>(NB);
    k_scan3<<<(N + 255) / 256, 256>>>(N);
    k_scatter<<<(EP + 255) / 256, 256>>>(E, EP);

    // self-loop attrs, CSR-ordered edge_attr
    k_loopattr<<<(N * 32 + 255) / 256, 256>>>(eattr, E, N);
    k_gatherea<<<(EP * 4 + 255) / 256, 256>>>(eattr, E, EP);

    // input projection -> g_h
    k_gemm128<<<(N + 15) / 16, 128>>>(x, in_w, in_b, N);

    for (int l = 0; l < 2; l++){
        const float* Wl_l  = Wl  + (size_t)l * 128 * 128;
        const float* bl_l  = bl  + (size_t)l * 128;
        const float* Wr_l  = Wr  + (size_t)l * 128 * 128;
        const float* br_l  = br  + (size_t)l * 128;
        const float* We_l  = We  + (size_t)l * 16 * 128;
        const float* att_l = att + (size_t)l * 128;
        const float* cb_l  = cb  + (size_t)l * 128;

        k_dualgemm<<<(N + 15) / 16, 128>>>(Wl_l, bl_l, Wr_l, br_l, N);
        k_edge_fused<<<296, 256>>>(We_l, att_l, cb_l, N);
    }

    k_final<<<(N + 7) / 8, 256>>>(lng, lnb, h1w, h1b, h2w, h2b, out, N);
}